// round 1
// baseline (speedup 1.0000x reference)
#include <cuda_runtime.h>
#include <math.h>

#define GRIDW 64
#define CIN   80
#define HID   64
#define SPR   96
#define NRAY  4096
#define NPTS  (NRAY*SPR)

// W1-projected planes: [p][y][x][j], j contiguous (64 floats per texel)
__device__ float g_PL[3*GRIDW*GRIDW*HID];
// per-point scratch: [point][8] = {rgb0,rgb1,rgb2,sigma, n0,n1,n2,pad}
__device__ float g_scr[NPTS*8];

// ---------------------------------------------------------------------------
// Kernel 1: PL[p][y][x][j] = sum_c planes[p][c][y][x] * W1[p*80+c][j]
// One block per (plane, row). smem-tiled: feats 80x64 + W1 slice 80x64.
// ---------------------------------------------------------------------------
__global__ void project_planes(const float* __restrict__ planes,
                               const float* __restrict__ W1) {
    const int blk = blockIdx.x;
    const int p = blk >> 6;        // plane 0..2
    const int y = blk & 63;        // row 0..63
    __shared__ float feats[CIN][GRIDW];
    __shared__ float w1s[CIN][HID];
    const int tid = threadIdx.x;
    for (int i = tid; i < CIN*GRIDW; i += 256) {
        int c = i >> 6, x = i & 63;
        feats[c][x] = planes[(((p*CIN + c)*GRIDW) + y)*GRIDW + x];
        w1s[c][x]   = W1[(p*CIN + c)*HID + x];
    }
    __syncthreads();
    #pragma unroll
    for (int k = 0; k < 16; k++) {
        int lin = tid + k*256;          // 0..4095
        int x = lin >> 6, j = lin & 63;
        float acc = 0.f;
        #pragma unroll 10
        for (int c = 0; c < CIN; c++)
            acc = fmaf(feats[c][x], w1s[c][j], acc);
        g_PL[(((p*GRIDW + y)*GRIDW) + x)*HID + j] = acc;
    }
}

// ---------------------------------------------------------------------------
// Kernel 2: one warp per point. 4 decodes (base + 3 FD offsets).
// Lane l owns hidden channels 2l, 2l+1 (float2 loads from g_PL -> coalesced).
// ---------------------------------------------------------------------------
__global__ __launch_bounds__(256) void point_kernel(
        const float* __restrict__ ro_all,
        const float* __restrict__ rd_all,
        const float* __restrict__ b1,
        const float* __restrict__ W2,
        const float* __restrict__ b2,
        float* __restrict__ grad_out) {
    const int lane  = threadIdx.x & 31;
    const int point = blockIdx.x * 8 + (threadIdx.x >> 5);
    const int ray   = point / SPR;
    const int s     = point - ray*SPR;

    const float ro0 = ro_all[ray*3+0], ro1 = ro_all[ray*3+1], ro2 = ro_all[ray*3+2];
    const float rd0 = rd_all[ray*3+0], rd1 = rd_all[ray*3+1], rd2 = rd_all[ray*3+2];

    // ray-box intersection
    float tn = 0.f, tf = 3.402823e38f;
    {
        float r[3] = {rd0, rd1, rd2};
        float o[3] = {ro0, ro1, ro2};
        #pragma unroll
        for (int i = 0; i < 3; i++) {
            float srd = (fabsf(r[i]) < 1e-9f) ? 1e-9f : r[i];
            float ta = (-0.6f - o[i]) / srd;
            float tb = ( 0.6f - o[i]) / srd;
            tn = fmaxf(tn, fminf(ta, tb));
            tf = fminf(tf, fmaxf(ta, tb));
        }
    }
    const float span  = fmaxf(tf - tn, 0.f);
    const float depth = tn + span * (((float)s + 0.5f) * (1.0f/96.0f));
    const float px = ro0 + depth*rd0;
    const float py = ro1 + depth*rd1;
    const float pz = ro2 + depth*rd2;

    const float b1a = b1[2*lane], b1b = b1[2*lane+1];
    const float w2a0 = W2[(2*lane)*4+0], w2a1 = W2[(2*lane)*4+1];
    const float w2a2 = W2[(2*lane)*4+2], w2a3 = W2[(2*lane)*4+3];
    const float w2b0 = W2[(2*lane+1)*4+0], w2b1 = W2[(2*lane+1)*4+1];
    const float w2b2 = W2[(2*lane+1)*4+2], w2b3 = W2[(2*lane+1)*4+3];

    float sdf_base = 0.f, rgb1v = 0.f, rgb2v = 0.f, rgb3v = 0.f;
    float sdfs[3];

    const float SCL = 2.0f / 1.2f;

    #pragma unroll
    for (int e = 0; e < 4; e++) {
        float qx = px, qy = py, qz = pz;
        if (e == 1) qx += 0.01f;
        if (e == 2) qy += 0.01f;
        if (e == 3) qz += 0.01f;
        if (e) {   // offsets get clipped to box (all components)
            qx = fminf(fmaxf(qx, -0.6f), 0.6f);
            qy = fminf(fmaxf(qy, -0.6f), 0.6f);
            qz = fminf(fmaxf(qz, -0.6f), 0.6f);
        }
        float h0 = b1a, h1 = b1b;
        const float ua[3] = {qx*SCL, qx*SCL, qy*SCL};
        const float va[3] = {qy*SCL, qz*SCL, qz*SCL};
        #pragma unroll
        for (int p = 0; p < 3; p++) {
            const float fx = (ua[p] + 1.f)*32.f - 0.5f;
            const float fy = (va[p] + 1.f)*32.f - 0.5f;
            const float fx0 = floorf(fx), fy0 = floorf(fy);
            const int x0 = (int)fx0, y0 = (int)fy0;
            const float wx = fx - fx0, wy = fy - fy0;
            #pragma unroll
            for (int t = 0; t < 4; t++) {
                const int dx = t & 1, dy = t >> 1;
                const int ix = x0 + dx, iy = y0 + dy;
                const float w = (dx ? wx : 1.f - wx) * (dy ? wy : 1.f - wy);
                const bool valid = (ix >= 0) && (ix < GRIDW) && (iy >= 0) && (iy < GRIDW);
                const int ixc = min(max(ix, 0), GRIDW-1);
                const int iyc = min(max(iy, 0), GRIDW-1);
                const float2 v = *reinterpret_cast<const float2*>(
                    &g_PL[(((p*GRIDW + iyc)*GRIDW) + ixc)*HID + 2*lane]);
                const float m = valid ? w : 0.f;
                h0 = fmaf(m, v.x, h0);
                h1 = fmaf(m, v.y, h1);
            }
        }
        h0 = fmaxf(h0, 0.f);
        h1 = fmaxf(h1, 0.f);

        float v0 = h0*w2a0 + h1*w2b0;
        if (e == 0) {
            float v1 = h0*w2a1 + h1*w2b1;
            float v2 = h0*w2a2 + h1*w2b2;
            float v3 = h0*w2a3 + h1*w2b3;
            #pragma unroll
            for (int off = 16; off; off >>= 1) {
                v0 += __shfl_xor_sync(0xffffffffu, v0, off);
                v1 += __shfl_xor_sync(0xffffffffu, v1, off);
                v2 += __shfl_xor_sync(0xffffffffu, v2, off);
                v3 += __shfl_xor_sync(0xffffffffu, v3, off);
            }
            sdf_base = v0 + b2[0];
            rgb1v = v1 + b2[1];
            rgb2v = v2 + b2[2];
            rgb3v = v3 + b2[3];
        } else {
            #pragma unroll
            for (int off = 16; off; off >>= 1)
                v0 += __shfl_xor_sync(0xffffffffu, v0, off);
            sdfs[e-1] = v0 + b2[0];
        }
    }

    if (lane == 0) {
        const float g0 = (sdfs[0] - sdf_base) * 100.f;
        const float g1 = (sdfs[1] - sdf_base) * 100.f;
        const float g2 = (sdfs[2] - sdf_base) * 100.f;
        grad_out[point*3 + 0] = g0;
        grad_out[point*3 + 1] = g1;
        grad_out[point*3 + 2] = g2;
        const float gn  = sqrtf(g0*g0 + g1*g1 + g2*g2);
        const float inv = 1.f / (gn + 1e-8f);
        const float shifted = sdf_base + sqrtf(px*px + py*py + pz*pz) - 0.5f;
        const float xs = -shifted * 80.f;
        const float sigma = fmaxf(xs, 0.f) + log1pf(expf(-fabsf(xs)));
        const float r1 = 1.002f / (1.f + expf(-rgb1v)) - 0.001f;
        const float r2 = 1.002f / (1.f + expf(-rgb2v)) - 0.001f;
        const float r3 = 1.002f / (1.f + expf(-rgb3v)) - 0.001f;
        float4 A; A.x = r1; A.y = r2; A.z = r3; A.w = sigma;
        float4 B; B.x = g0*inv; B.y = g1*inv; B.z = g2*inv; B.w = 0.f;
        *reinterpret_cast<float4*>(&g_scr[point*8    ]) = A;
        *reinterpret_cast<float4*>(&g_scr[point*8 + 4]) = B;
    }
}

// ---------------------------------------------------------------------------
// Kernel 3: per-ray compositing (sequential cumprod over S=96)
// ---------------------------------------------------------------------------
__global__ void composite(const float* __restrict__ ro_all,
                          const float* __restrict__ rd_all,
                          float* __restrict__ out) {
    const int r = blockIdx.x * blockDim.x + threadIdx.x;
    if (r >= NRAY) return;

    float tn = 0.f, tf = 3.402823e38f;
    #pragma unroll
    for (int i = 0; i < 3; i++) {
        float rdv = rd_all[r*3+i];
        float ov  = ro_all[r*3+i];
        float srd = (fabsf(rdv) < 1e-9f) ? 1e-9f : rdv;
        float ta = (-0.6f - ov) / srd;
        float tb = ( 0.6f - ov) / srd;
        tn = fmaxf(tn, fminf(ta, tb));
        tf = fminf(tf, fmaxf(ta, tb));
    }
    const float span  = fmaxf(tf - tn, 0.f);
    const float delta = span * (1.0f/96.0f);

    float T = 1.f;
    float rgb0 = 0.f, rgb1 = 0.f, rgb2 = 0.f, dep = 0.f, ws = 0.f;
    float n0 = 0.f, n1 = 0.f, n2 = 0.f;
    for (int s = 0; s < SPR; s++) {
        const float4 A = *reinterpret_cast<const float4*>(&g_scr[(size_t)(r*SPR + s)*8]);
        const float4 B = *reinterpret_cast<const float4*>(&g_scr[(size_t)(r*SPR + s)*8 + 4]);
        const float alpha = 1.f - expf(-A.w * delta);
        const float w = alpha * T;
        rgb0 += w * A.x; rgb1 += w * A.y; rgb2 += w * A.z;
        dep  += w * (tn + span * (((float)s + 0.5f) * (1.0f/96.0f)));
        ws   += w;
        n0   += w * B.x; n1 += w * B.y; n2 += w * B.z;
        T *= (1.f - alpha + 1e-10f);
    }
    const float bg = 1.f - ws;
    rgb0 += bg; rgb1 += bg; rgb2 += bg;

    const float nn  = sqrtf(n0*n0 + n1*n1 + n2*n2);
    const float inv = 1.f / (nn + 1e-8f);
    const float o0 = ((n0*inv) + 1.f) * 0.5f * ws;
    const float o1 = ((n1*inv) + 1.f) * 0.5f * ws;
    const float o2 = ((n2*inv) + 1.f) * 0.5f * ws;

    // output layout: rgb[3*4096] | depth[4096] | opacity[4096] | normal[3*4096] | sdf_grad
    out[r]              = rgb0;
    out[ 4096 + r]      = rgb1;
    out[ 8192 + r]      = rgb2;
    out[12288 + r]      = dep;
    out[16384 + r]      = ws;
    out[20480 + r]      = o0;
    out[24576 + r]      = o1;
    out[28672 + r]      = o2;
}

// ---------------------------------------------------------------------------
extern "C" void kernel_launch(void* const* d_in, const int* in_sizes, int n_in,
                              void* d_out, int out_size) {
    const float* planes = (const float*)d_in[0];
    const float* ro     = (const float*)d_in[1];
    const float* rd     = (const float*)d_in[2];
    const float* W1     = (const float*)d_in[3];
    const float* b1     = (const float*)d_in[4];
    const float* W2     = (const float*)d_in[5];
    const float* b2     = (const float*)d_in[6];
    float* out = (float*)d_out;

    project_planes<<<3*GRIDW, 256>>>(planes, W1);
    point_kernel<<<NPTS/8, 256>>>(ro, rd, b1, W2, b2, out + 32768);
    composite<<<(NRAY + 255)/256, 256>>>(ro, rd, out);
}

// round 2
// speedup vs baseline: 1.8441x; 1.8441x over previous
#include <cuda_runtime.h>
#include <math.h>

#define GRIDW 64
#define CIN   80
#define HID   64
#define SPR   96
#define NRAY  4096
#define NPTS  (NRAY*SPR)

// W1-projected planes: [p][y][x][j], j contiguous (64 floats per texel)
__device__ float g_PL[3*GRIDW*GRIDW*HID];
// per-point scratch: [point][8] = {rgb0,rgb1,rgb2,sigma, n0,n1,n2,pad}
__device__ float g_scr[NPTS*8];
// per-ray {tn, span}
__device__ float g_ray[NRAY*2];

// ---------------------------------------------------------------------------
// Kernel 0: per-ray box intersection (full-precision div, done once per ray)
// ---------------------------------------------------------------------------
__global__ void ray_setup(const float* __restrict__ ro_all,
                          const float* __restrict__ rd_all) {
    const int r = blockIdx.x * blockDim.x + threadIdx.x;
    if (r >= NRAY) return;
    float tn = 0.f, tf = 3.402823e38f;
    #pragma unroll
    for (int i = 0; i < 3; i++) {
        float rdv = rd_all[r*3+i];
        float ov  = ro_all[r*3+i];
        float srd = (fabsf(rdv) < 1e-9f) ? 1e-9f : rdv;
        float ta = (-0.6f - ov) / srd;
        float tb = ( 0.6f - ov) / srd;
        tn = fmaxf(tn, fminf(ta, tb));
        tf = fminf(tf, fmaxf(ta, tb));
    }
    g_ray[r*2]   = tn;
    g_ray[r*2+1] = fmaxf(tf - tn, 0.f);
}

// ---------------------------------------------------------------------------
// Kernel 1: PL[p][y][x][j] = sum_c planes[p][c][y][x] * W1[p*80+c][j]
// block=(plane,row); thread=(x, jgroup of 16): 16 FMA per 5 LDS.
// ---------------------------------------------------------------------------
__global__ void project_planes(const float* __restrict__ planes,
                               const float* __restrict__ W1) {
    const int blk = blockIdx.x;
    const int p = blk >> 6;
    const int y = blk & 63;
    __shared__ float feats[CIN][GRIDW];
    __shared__ float w1s[CIN][HID];
    const int tid = threadIdx.x;
    for (int i = tid; i < CIN*GRIDW; i += 256) {
        int c = i >> 6, x = i & 63;
        feats[c][x] = planes[(((p*CIN + c)*GRIDW) + y)*GRIDW + x];
        w1s[c][x]   = W1[(p*CIN + c)*HID + x];
    }
    __syncthreads();
    const int x  = tid >> 2;        // 0..63
    const int jg = (tid & 3) * 16;  // 0,16,32,48
    float acc[16];
    #pragma unroll
    for (int k = 0; k < 16; k++) acc[k] = 0.f;
    #pragma unroll 8
    for (int c = 0; c < CIN; c++) {
        const float f = feats[c][x];
        #pragma unroll
        for (int q = 0; q < 4; q++) {
            float4 w = *reinterpret_cast<const float4*>(&w1s[c][jg + q*4]);
            acc[q*4+0] = fmaf(f, w.x, acc[q*4+0]);
            acc[q*4+1] = fmaf(f, w.y, acc[q*4+1]);
            acc[q*4+2] = fmaf(f, w.z, acc[q*4+2]);
            acc[q*4+3] = fmaf(f, w.w, acc[q*4+3]);
        }
    }
    float* dst = &g_PL[(((p*GRIDW + y)*GRIDW) + x)*HID + jg];
    #pragma unroll
    for (int q = 0; q < 4; q++) {
        float4 v; v.x = acc[q*4+0]; v.y = acc[q*4+1]; v.z = acc[q*4+2]; v.w = acc[q*4+3];
        *reinterpret_cast<float4*>(dst + q*4) = v;
    }
}

// ---------------------------------------------------------------------------
// bilinear sample of 4 channels (c0..c0+3) from projected plane, accumulate
// ---------------------------------------------------------------------------
__device__ __forceinline__ void sample_accum(const float* __restrict__ PLp,
                                             float u, float v, int c0,
                                             float4& P) {
    const float fx  = fmaf(u, 32.f, 31.5f);
    const float fy  = fmaf(v, 32.f, 31.5f);
    const float fxf = floorf(fx), fyf = floorf(fy);
    const int   x0  = (int)fxf,   y0  = (int)fyf;
    const float wx  = fx - fxf,   wy  = fy - fyf;
    const int x0c = max(x0, 0),   x1c = min(x0 + 1, GRIDW-1);
    const int y0c = max(y0, 0),   y1c = min(y0 + 1, GRIDW-1);
    const float mx0 = (x0 >= 0)        ? (1.f - wx) : 0.f;
    const float mx1 = (x0 <  GRIDW-1)  ? wx         : 0.f;
    const float my0 = (y0 >= 0)        ? (1.f - wy) : 0.f;
    const float my1 = (y0 <  GRIDW-1)  ? wy         : 0.f;
    const float* r0 = PLp + (y0c * GRIDW) * HID + c0;
    const float* r1 = PLp + (y1c * GRIDW) * HID + c0;
    const float4 t00 = *reinterpret_cast<const float4*>(r0 + x0c * HID);
    const float4 t10 = *reinterpret_cast<const float4*>(r0 + x1c * HID);
    const float4 t01 = *reinterpret_cast<const float4*>(r1 + x0c * HID);
    const float4 t11 = *reinterpret_cast<const float4*>(r1 + x1c * HID);
    const float w00 = mx0*my0, w10 = mx1*my0, w01 = mx0*my1, w11 = mx1*my1;
    P.x = fmaf(w00, t00.x, fmaf(w10, t10.x, fmaf(w01, t01.x, fmaf(w11, t11.x, P.x))));
    P.y = fmaf(w00, t00.y, fmaf(w10, t10.y, fmaf(w01, t01.y, fmaf(w11, t11.y, P.y))));
    P.z = fmaf(w00, t00.z, fmaf(w10, t10.z, fmaf(w01, t01.z, fmaf(w11, t11.z, P.z))));
    P.w = fmaf(w00, t00.w, fmaf(w10, t10.w, fmaf(w01, t01.w, fmaf(w11, t11.w, P.w))));
}

__device__ __forceinline__ float reduce16(float v) {
    #pragma unroll
    for (int off = 8; off; off >>= 1)
        v += __shfl_xor_sync(0xffffffffu, v, off);
    return v;
}

// ---------------------------------------------------------------------------
// Kernel 2: 2 points per warp, 16 lanes/point, 4 channels/lane (float4).
// Base decode + 3 FD decodes; each FD decode resamples only 2 planes.
// ---------------------------------------------------------------------------
__global__ __launch_bounds__(256) void point_kernel(
        const float* __restrict__ ro_all,
        const float* __restrict__ rd_all,
        const float* __restrict__ b1,
        const float* __restrict__ W2,
        const float* __restrict__ b2,
        float* __restrict__ grad_out) {
    const int lane = threadIdx.x & 31;
    const int sub  = lane & 15;
    const int half = lane >> 4;
    const int point = blockIdx.x * 16 + (threadIdx.x >> 5) * 2 + half;
    const int ray   = point / SPR;
    const int s     = point - ray * SPR;
    const int c0    = sub * 4;

    const float tn   = g_ray[2*ray];
    const float span = g_ray[2*ray + 1];
    const float depth = tn + span * (((float)s + 0.5f) * (1.0f/96.0f));
    const float px = fmaf(depth, rd_all[ray*3+0], ro_all[ray*3+0]);
    const float py = fmaf(depth, rd_all[ray*3+1], ro_all[ray*3+1]);
    const float pz = fmaf(depth, rd_all[ray*3+2], ro_all[ray*3+2]);

    const float4 b1v = *reinterpret_cast<const float4*>(b1 + c0);
    const float4 w2r0 = reinterpret_cast<const float4*>(W2)[c0 + 0];
    const float4 w2r1 = reinterpret_cast<const float4*>(W2)[c0 + 1];
    const float4 w2r2 = reinterpret_cast<const float4*>(W2)[c0 + 2];
    const float4 w2r3 = reinterpret_cast<const float4*>(W2)[c0 + 3];

    const float SCL = 2.0f / 1.2f;
    const float ux = px * SCL, uy = py * SCL, uz = pz * SCL;
    const float* PL0 = g_PL;
    const float* PL1 = g_PL + GRIDW*GRIDW*HID;
    const float* PL2 = g_PL + 2*GRIDW*GRIDW*HID;

    // --- base decode: 3 plane partials (kept for reuse) ---
    float4 P0 = {0,0,0,0}, P1 = {0,0,0,0}, P2 = {0,0,0,0};
    sample_accum(PL0, ux, uy, c0, P0);   // plane0: (x,y)
    sample_accum(PL1, ux, uz, c0, P1);   // plane1: (x,z)
    sample_accum(PL2, uy, uz, c0, P2);   // plane2: (y,z)

    float h0 = fmaxf(b1v.x + P0.x + P1.x + P2.x, 0.f);
    float h1 = fmaxf(b1v.y + P0.y + P1.y + P2.y, 0.f);
    float h2 = fmaxf(b1v.z + P0.z + P1.z + P2.z, 0.f);
    float h3 = fmaxf(b1v.w + P0.w + P1.w + P2.w, 0.f);

    float v0 = h0*w2r0.x + h1*w2r1.x + h2*w2r2.x + h3*w2r3.x;
    float v1 = h0*w2r0.y + h1*w2r1.y + h2*w2r2.y + h3*w2r3.y;
    float v2 = h0*w2r0.z + h1*w2r1.z + h2*w2r2.z + h3*w2r3.z;
    float v3 = h0*w2r0.w + h1*w2r1.w + h2*w2r2.w + h3*w2r3.w;
    const float sdf_base = reduce16(v0) + b2[0];
    const float rgb1v    = reduce16(v1) + b2[1];
    const float rgb2v    = reduce16(v2) + b2[2];
    const float rgb3v    = reduce16(v3) + b2[3];

    // --- FD decodes: resample only the 2 planes containing the offset axis ---
    float sdfs[3];
    {   // e=1: x+eps  -> planes 0,1 change, reuse P2
        const float q = fminf(fmaxf(px + 0.01f, -0.6f), 0.6f) * SCL;
        float4 Q0 = {0,0,0,0}, Q1 = {0,0,0,0};
        sample_accum(PL0, q, uy, c0, Q0);
        sample_accum(PL1, q, uz, c0, Q1);
        float a0 = fmaxf(b1v.x + Q0.x + Q1.x + P2.x, 0.f);
        float a1 = fmaxf(b1v.y + Q0.y + Q1.y + P2.y, 0.f);
        float a2 = fmaxf(b1v.z + Q0.z + Q1.z + P2.z, 0.f);
        float a3 = fmaxf(b1v.w + Q0.w + Q1.w + P2.w, 0.f);
        sdfs[0] = reduce16(a0*w2r0.x + a1*w2r1.x + a2*w2r2.x + a3*w2r3.x) + b2[0];
    }
    {   // e=2: y+eps  -> planes 0,2 change, reuse P1
        const float q = fminf(fmaxf(py + 0.01f, -0.6f), 0.6f) * SCL;
        float4 Q0 = {0,0,0,0}, Q2 = {0,0,0,0};
        sample_accum(PL0, ux, q, c0, Q0);
        sample_accum(PL2, q, uz, c0, Q2);
        float a0 = fmaxf(b1v.x + Q0.x + P1.x + Q2.x, 0.f);
        float a1 = fmaxf(b1v.y + Q0.y + P1.y + Q2.y, 0.f);
        float a2 = fmaxf(b1v.z + Q0.z + P1.z + Q2.z, 0.f);
        float a3 = fmaxf(b1v.w + Q0.w + P1.w + Q2.w, 0.f);
        sdfs[1] = reduce16(a0*w2r0.x + a1*w2r1.x + a2*w2r2.x + a3*w2r3.x) + b2[0];
    }
    {   // e=3: z+eps  -> planes 1,2 change, reuse P0
        const float q = fminf(fmaxf(pz + 0.01f, -0.6f), 0.6f) * SCL;
        float4 Q1 = {0,0,0,0}, Q2 = {0,0,0,0};
        sample_accum(PL1, ux, q, c0, Q1);
        sample_accum(PL2, uy, q, c0, Q2);
        float a0 = fmaxf(b1v.x + P0.x + Q1.x + Q2.x, 0.f);
        float a1 = fmaxf(b1v.y + P0.y + Q1.y + Q2.y, 0.f);
        float a2 = fmaxf(b1v.z + P0.z + Q1.z + Q2.z, 0.f);
        float a3 = fmaxf(b1v.w + P0.w + Q1.w + Q2.w, 0.f);
        sdfs[2] = reduce16(a0*w2r0.x + a1*w2r1.x + a2*w2r2.x + a3*w2r3.x) + b2[0];
    }

    if (sub == 0) {
        const float g0 = (sdfs[0] - sdf_base) * 100.f;
        const float g1 = (sdfs[1] - sdf_base) * 100.f;
        const float g2 = (sdfs[2] - sdf_base) * 100.f;
        grad_out[point*3 + 0] = g0;
        grad_out[point*3 + 1] = g1;
        grad_out[point*3 + 2] = g2;
        const float gn  = sqrtf(g0*g0 + g1*g1 + g2*g2);
        const float inv = 1.f / (gn + 1e-8f);
        const float shifted = sdf_base + sqrtf(px*px + py*py + pz*pz) - 0.5f;
        const float xs = -shifted * 80.f;
        const float sigma = fmaxf(xs, 0.f) + log1pf(expf(-fabsf(xs)));
        const float r1 = 1.002f / (1.f + expf(-rgb1v)) - 0.001f;
        const float r2 = 1.002f / (1.f + expf(-rgb2v)) - 0.001f;
        const float r3 = 1.002f / (1.f + expf(-rgb3v)) - 0.001f;
        float4 A; A.x = r1; A.y = r2; A.z = r3; A.w = sigma;
        float4 B; B.x = g0*inv; B.y = g1*inv; B.z = g2*inv; B.w = 0.f;
        *reinterpret_cast<float4*>(&g_scr[point*8    ]) = A;
        *reinterpret_cast<float4*>(&g_scr[point*8 + 4]) = B;
    }
}

// ---------------------------------------------------------------------------
// Kernel 3: per-ray compositing (sequential cumprod over S=96)
// ---------------------------------------------------------------------------
__global__ void composite(float* __restrict__ out) {
    const int r = blockIdx.x * blockDim.x + threadIdx.x;
    if (r >= NRAY) return;

    const float tn   = g_ray[2*r];
    const float span = g_ray[2*r + 1];
    const float delta = span * (1.0f/96.0f);

    float T = 1.f;
    float rgb0 = 0.f, rgb1 = 0.f, rgb2 = 0.f, dep = 0.f, ws = 0.f;
    float n0 = 0.f, n1 = 0.f, n2 = 0.f;
    for (int s = 0; s < SPR; s++) {
        const float4 A = *reinterpret_cast<const float4*>(&g_scr[(size_t)(r*SPR + s)*8]);
        const float4 B = *reinterpret_cast<const float4*>(&g_scr[(size_t)(r*SPR + s)*8 + 4]);
        const float alpha = 1.f - expf(-A.w * delta);
        const float w = alpha * T;
        rgb0 += w * A.x; rgb1 += w * A.y; rgb2 += w * A.z;
        dep  += w * (tn + span * (((float)s + 0.5f) * (1.0f/96.0f)));
        ws   += w;
        n0   += w * B.x; n1 += w * B.y; n2 += w * B.z;
        T *= (1.f - alpha + 1e-10f);
    }
    const float bg = 1.f - ws;
    rgb0 += bg; rgb1 += bg; rgb2 += bg;

    const float nn  = sqrtf(n0*n0 + n1*n1 + n2*n2);
    const float inv = 1.f / (nn + 1e-8f);
    const float o0 = ((n0*inv) + 1.f) * 0.5f * ws;
    const float o1 = ((n1*inv) + 1.f) * 0.5f * ws;
    const float o2 = ((n2*inv) + 1.f) * 0.5f * ws;

    out[r]         = rgb0;
    out[ 4096 + r] = rgb1;
    out[ 8192 + r] = rgb2;
    out[12288 + r] = dep;
    out[16384 + r] = ws;
    out[20480 + r] = o0;
    out[24576 + r] = o1;
    out[28672 + r] = o2;
}

// ---------------------------------------------------------------------------
extern "C" void kernel_launch(void* const* d_in, const int* in_sizes, int n_in,
                              void* d_out, int out_size) {
    const float* planes = (const float*)d_in[0];
    const float* ro     = (const float*)d_in[1];
    const float* rd     = (const float*)d_in[2];
    const float* W1     = (const float*)d_in[3];
    const float* b1     = (const float*)d_in[4];
    const float* W2     = (const float*)d_in[5];
    const float* b2     = (const float*)d_in[6];
    float* out = (float*)d_out;

    ray_setup<<<(NRAY + 255)/256, 256>>>(ro, rd);
    project_planes<<<3*GRIDW, 256>>>(planes, W1);
    point_kernel<<<NPTS/16, 256>>>(ro, rd, b1, W2, b2, out + 32768);
    composite<<<(NRAY + 255)/256, 256>>>(out);
}